// round 16
// baseline (speedup 1.0000x reference)
#include <cuda_runtime.h>
#include <cuda_bf16.h>
#include <math.h>
#include <float.h>
#include <stdint.h>

#define NN 4096
#define DD 2048
#define HH 256
#define HEADS 4
#define K3DD (3*2048)
#define K2HH (2*256)
#define NQK 2048
#define SPW 2048
#define PAIRS 8256   // 128*129/2

// ---------------- static device scratch ----------------
__device__ float g_QK[(size_t)NN * NQK];
__device__ float g_qn[HEADS * NN];
__device__ float g_kn[HEADS * NN];
__device__ float g_uth[HEADS * NN];    // 30th-smallest u per row
__device__ float g_inv2[HEADS * NN];   // 1/(md+1e-10)^2 per row
__device__ float g_A[(size_t)HEADS * NN * NN];
__device__ float g_M[(size_t)HEADS * NN * NN];

__device__ int   g_cols[(size_t)HEADS * NN * SPW];
__device__ float g_wv[(size_t)HEADS * NN * SPW];
__device__ int   g_cnt[HEADS * NN];
__device__ float g_Z[HEADS * NN];

__device__ float g_m[HEADS * 6 * NN];
__device__ float g_g[HEADS * 5];
__device__ float g_rpart[(size_t)HEADS * 32 * 6 * DD];
__device__ float g_r[HEADS * 6 * DD];
__device__ float g_s[HEADS * 7 * DD];

__device__ __nv_bfloat16 s_Xa[(size_t)NN * K3DD];
__device__ __nv_bfloat16 s_Wall[(size_t)NQK * K3DD];
__device__ __nv_bfloat16 s_Qa[(size_t)HEADS * NN * K2HH];
__device__ __nv_bfloat16 s_Kb[(size_t)HEADS * NN * K2HH];

// shared u formula — must be bit-identical in select and afftrans
__device__ __forceinline__ float usq(float qni, float knj, float g) {
    float t = __fadd_rn(qni, knj);
    t = __fadd_rn(t, __fmul_rn(-2.0f, g));
    t = fmaxf(t, 0.0f);
    return __fadd_rn(t, 1e-10f);
}

// ---------------- batched mma.sync NT GEMM: 128x256 CTA, 8 warps, 64x64 warp ----------------
#define BM 128
#define BN 256
#define BK 64
#define STAGES 3
#define PAD 72
#define A_STAGE (BM * PAD * 2)
#define B_STAGE (BN * PAD * 2)
#define STAGE_BYTES (A_STAGE + B_STAGE)
#define GEMM_SMEM (STAGES * STAGE_BYTES)

__device__ __forceinline__ uint32_t smem_u32(const void* p) {
    uint32_t a;
    asm("{ .reg .u64 t; cvta.to.shared.u64 t, %1; cvt.u32.u64 %0, t; }" : "=r"(a) : "l"(p));
    return a;
}
#define CP_ASYNC16(sa, ga) \
    asm volatile("cp.async.cg.shared.global [%0], [%1], 16;" :: "r"(sa), "l"(ga))
#define CP_COMMIT() asm volatile("cp.async.commit_group;" ::: "memory")
#define CP_WAIT1()  asm volatile("cp.async.wait_group 1;" ::: "memory")
#define CP_WAIT0()  asm volatile("cp.async.wait_group 0;" ::: "memory")
#define LDSM_X4(r0, r1, r2, r3, a) \
    asm volatile("ldmatrix.sync.aligned.m8n8.x4.shared.b16 {%0,%1,%2,%3}, [%4];" \
        : "=r"(r0), "=r"(r1), "=r"(r2), "=r"(r3) : "r"(a))
#define MMA16816(c, a0, a1, a2, a3, b0, b1) \
    asm volatile("mma.sync.aligned.m16n8k16.row.col.f32.bf16.bf16.f32 " \
        "{%0,%1,%2,%3}, {%4,%5,%6,%7}, {%8,%9}, {%0,%1,%2,%3};" \
        : "+f"((c)[0]), "+f"((c)[1]), "+f"((c)[2]), "+f"((c)[3]) \
        : "r"(a0), "r"(a1), "r"(a2), "r"(a3), "r"(b0), "r"(b1))

__global__ __launch_bounds__(256) void mma_gemm_nt(
    const __nv_bfloat16* __restrict__ Ab, const __nv_bfloat16* __restrict__ Bb,
    float* __restrict__ Cb, int M, int N, int K, int ldc,
    size_t strideA, size_t strideB, size_t strideC,
    const float* __restrict__ bq, const float* __restrict__ bk)
{
    extern __shared__ __align__(128) char smem[];
    const uint32_t sbase = smem_u32(smem);
    const int tid = threadIdx.x;
    const int wid = tid >> 5;
    const int lane = tid & 31;
    const int wm = (wid & 1) * 64;
    const int wn = (wid >> 1) * 64;

    const __nv_bfloat16* A = Ab + blockIdx.z * strideA;
    const __nv_bfloat16* B = Bb + blockIdx.z * strideB;
    float* C = Cb + blockIdx.z * strideC;

    const int nbx = gridDim.x;
    int id = blockIdx.y * nbx + blockIdx.x;
    int grp = id / (8 * nbx);
    int rem = id - grp * (8 * nbx);
    const int m0 = (grp * 8 + (rem & 7)) * BM;
    const int n0 = (rem >> 3) * BN;

    const __nv_bfloat16* gA = A + (size_t)m0 * K;
    const __nv_bfloat16* gB = B + (size_t)n0 * K;

    const int lrow = tid >> 3;
    const int lcol = (tid & 7) << 3;

    float acc[4][8][4];
    #pragma unroll
    for (int i = 0; i < 4; i++)
        #pragma unroll
        for (int j = 0; j < 8; j++)
            #pragma unroll
            for (int q = 0; q < 4; q++) acc[i][j][q] = 0.0f;

    const int KT = K / BK;

    #pragma unroll
    for (int s = 0; s < STAGES - 1; s++) {
        const int k0 = s * BK;
        uint32_t sa = sbase + s * STAGE_BYTES;
        uint32_t sb = sa + A_STAGE;
        #pragma unroll
        for (int h = 0; h < 4; h++) {
            int r = lrow + h * 32;
            CP_ASYNC16(sa + (uint32_t)(r * PAD + lcol) * 2, gA + (size_t)r * K + k0 + lcol);
        }
        #pragma unroll
        for (int h = 0; h < 8; h++) {
            int r = lrow + h * 32;
            CP_ASYNC16(sb + (uint32_t)(r * PAD + lcol) * 2, gB + (size_t)r * K + k0 + lcol);
        }
        CP_COMMIT();
    }

    const int a_row = wm + (lane & 15);
    const int a_half = (lane >> 4) << 3;
    const int b_row = wn + ((lane >> 4) << 3) + (lane & 7);
    const int b_half = ((lane >> 3) & 1) << 3;

    for (int kt = 0; kt < KT; kt++) {
        CP_WAIT1();
        __syncthreads();

        if (kt + STAGES - 1 < KT) {
            const int s = (kt + STAGES - 1) % STAGES;
            const int k0 = (kt + STAGES - 1) * BK;
            uint32_t sa = sbase + s * STAGE_BYTES;
            uint32_t sb = sa + A_STAGE;
            #pragma unroll
            for (int h = 0; h < 4; h++) {
                int r = lrow + h * 32;
                CP_ASYNC16(sa + (uint32_t)(r * PAD + lcol) * 2, gA + (size_t)r * K + k0 + lcol);
            }
            #pragma unroll
            for (int h = 0; h < 8; h++) {
                int r = lrow + h * 32;
                CP_ASYNC16(sb + (uint32_t)(r * PAD + lcol) * 2, gB + (size_t)r * K + k0 + lcol);
            }
        }
        CP_COMMIT();

        const int s = kt % STAGES;
        const uint32_t sa = sbase + s * STAGE_BYTES;
        const uint32_t sb = sa + A_STAGE;

        #pragma unroll
        for (int kk = 0; kk < 4; kk++) {
            uint32_t a0[4], a1[4], a2[4], a3[4];
            #pragma unroll
            for (int mt = 0; mt < 4; mt++) {
                uint32_t addr = sa + (uint32_t)((a_row + mt * 16) * PAD + kk * 16 + a_half) * 2;
                LDSM_X4(a0[mt], a1[mt], a2[mt], a3[mt], addr);
            }
            uint32_t b[8][2];
            #pragma unroll
            for (int g = 0; g < 4; g++) {
                uint32_t addr = sb + (uint32_t)((b_row + g * 16) * PAD + kk * 16 + b_half) * 2;
                uint32_t r0, r1, r2, r3;
                LDSM_X4(r0, r1, r2, r3, addr);
                b[g * 2 + 0][0] = r0; b[g * 2 + 0][1] = r1;
                b[g * 2 + 1][0] = r2; b[g * 2 + 1][1] = r3;
            }
            #pragma unroll
            for (int mt = 0; mt < 4; mt++)
                #pragma unroll
                for (int nt = 0; nt < 8; nt++)
                    MMA16816(acc[mt][nt], a0[mt], a1[mt], a2[mt], a3[mt],
                             b[nt][0], b[nt][1]);
        }
        __syncthreads();
    }
    CP_WAIT0();

    const int er = lane >> 2;
    const int ec = (lane & 3) << 1;
    #pragma unroll
    for (int mt = 0; mt < 4; mt++) {
        #pragma unroll
        for (int nt = 0; nt < 8; nt++) {
            int col = n0 + wn + nt * 8 + ec;
            float b0 = 0.0f, b1 = 0.0f;
            if (bq) {
                b0 = (col < 1024) ? bq[col] : bk[col - 1024];
                b1 = (col + 1 < 1024) ? bq[col + 1] : bk[col + 1 - 1024];
            }
            #pragma unroll
            for (int half = 0; half < 2; half++) {
                int row = m0 + wm + mt * 16 + er + half * 8;
                float* Cp = C + (size_t)row * ldc + col;
                *(float2*)Cp = make_float2(acc[mt][nt][half * 2 + 0] + b0,
                                           acc[mt][nt][half * 2 + 1] + b1);
            }
        }
    }
}

// ---------------- vectorized splits ----------------
__device__ __forceinline__ unsigned short bfu(__nv_bfloat16 v) {
    return *reinterpret_cast<unsigned short*>(&v);
}

__global__ void split_kernel4(const float4* __restrict__ src, ushort4* __restrict__ dst,
                              int total4, int logC4, int lo_mid)
{
    int idx = blockIdx.x * blockDim.x + threadIdx.x;
    if (idx >= total4) return;
    int C4 = 1 << logC4;
    int r = idx >> logC4;
    int c = idx & (C4 - 1);
    float4 x = src[idx];
    __nv_bfloat16 h0 = __float2bfloat16(x.x), h1 = __float2bfloat16(x.y);
    __nv_bfloat16 h2 = __float2bfloat16(x.z), h3 = __float2bfloat16(x.w);
    __nv_bfloat16 l0 = __float2bfloat16(x.x - __bfloat162float(h0));
    __nv_bfloat16 l1 = __float2bfloat16(x.y - __bfloat162float(h1));
    __nv_bfloat16 l2 = __float2bfloat16(x.z - __bfloat162float(h2));
    __nv_bfloat16 l3 = __float2bfloat16(x.w - __bfloat162float(h3));
    ushort4 hh = make_ushort4(bfu(h0), bfu(h1), bfu(h2), bfu(h3));
    ushort4 ll = make_ushort4(bfu(l0), bfu(l1), bfu(l2), bfu(l3));
    size_t base = (size_t)r * 3 * C4 + c;
    dst[base] = hh;
    dst[base + C4] = lo_mid ? ll : hh;
    dst[base + 2 * C4] = lo_mid ? hh : ll;
}

__global__ void split2_strided4(const float* __restrict__ QK, int base_off,
                                ushort4* __restrict__ dst, int lo_second)
{
    int idx = blockIdx.x * blockDim.x + threadIdx.x;
    if (idx >= NN * (HH / 4)) return;
    int h = blockIdx.y;
    int r = idx >> 6;
    int c = idx & 63;
    float4 x = *(const float4*)(QK + (size_t)r * NQK + base_off + h * HH + c * 4);
    __nv_bfloat16 h0 = __float2bfloat16(x.x), h1 = __float2bfloat16(x.y);
    __nv_bfloat16 h2 = __float2bfloat16(x.z), h3 = __float2bfloat16(x.w);
    ushort4 hh = make_ushort4(bfu(h0), bfu(h1), bfu(h2), bfu(h3));
    ushort4 sec = hh;
    if (lo_second) {
        __nv_bfloat16 l0 = __float2bfloat16(x.x - __bfloat162float(h0));
        __nv_bfloat16 l1 = __float2bfloat16(x.y - __bfloat162float(h1));
        __nv_bfloat16 l2 = __float2bfloat16(x.z - __bfloat162float(h2));
        __nv_bfloat16 l3 = __float2bfloat16(x.w - __bfloat162float(h3));
        sec = make_ushort4(bfu(l0), bfu(l1), bfu(l2), bfu(l3));
    }
    size_t base = (size_t)h * NN * 128 + (size_t)r * 128 + c;
    dst[base] = hh;
    dst[base + 64] = sec;
}

// ---------------- batched: blockIdx.y = head ----------------
__global__ void rownorm_b(const float* __restrict__ QK,
                          float* __restrict__ qn, float* __restrict__ kn)
{
    int i = blockIdx.x;
    int h = blockIdx.y;
    int tid = threadIdx.x;
    __shared__ float sq[256];
    __shared__ float sk[256];
    float q = QK[(size_t)i * NQK + h * HH + tid];
    float k = QK[(size_t)i * NQK + 1024 + h * HH + tid];
    sq[tid] = q * q;
    sk[tid] = k * k;
    __syncthreads();
    for (int s = 128; s > 0; s >>= 1) {
        if (tid < s) { sq[tid] += sq[tid + s]; sk[tid] += sk[tid + s]; }
        __syncthreads();
    }
    if (tid == 0) { qn[h * NN + i] = sq[0]; kn[h * NN + i] = sk[0]; }
}

// ---------------- register-resident selection on u (no per-element sqrt) ----------------
__global__ __launch_bounds__(256) void select_b(
    const float* __restrict__ Ab,
    const float* __restrict__ qn, const float* __restrict__ kn,
    float* __restrict__ uth_out, float* __restrict__ inv2_out)
{
    int i = blockIdx.x;
    int h = blockIdx.y;
    int tid = threadIdx.x;
    int lane = tid & 31;
    int wid = tid >> 5;
    const float* G = Ab + (size_t)h * NN * NN + (size_t)i * NN;
    const float* knh = kn + h * NN;
    float qni = qn[h * NN + i];

    float dv[16];
    const float4* G4 = (const float4*)G;
    const float4* K4 = (const float4*)knh;
    #pragma unroll
    for (int b = 0; b < 4; b++) {
        float4 g = G4[tid * 4 + b];
        float4 k4 = K4[tid * 4 + b];
        dv[b * 4 + 0] = usq(qni, k4.x, g.x);
        dv[b * 4 + 1] = usq(qni, k4.y, g.y);
        dv[b * 4 + 2] = usq(qni, k4.z, g.z);
        dv[b * 4 + 3] = usq(qni, k4.w, g.w);
    }

    __shared__ float wvv[8];
    __shared__ int wii[8];
    __shared__ float winv_s;
    __shared__ int wini_s;
    float sel10 = 0.0f, sel29 = 0.0f;

    for (int it = 0; it < 30; it++) {
        float v = dv[0];
        int li = 0;
        #pragma unroll
        for (int k = 1; k < 16; k++)
            if (dv[k] < v) { v = dv[k]; li = k; }
        int gi = tid * 16 + li;
        #pragma unroll
        for (int o = 16; o; o >>= 1) {
            float v2 = __shfl_down_sync(0xffffffffu, v, o);
            int i2 = __shfl_down_sync(0xffffffffu, gi, o);
            if (v2 < v || (v2 == v && i2 < gi)) { v = v2; gi = i2; }
        }
        if (lane == 0) { wvv[wid] = v; wii[wid] = gi; }
        __syncthreads();
        if (tid == 0) {
            float bv = wvv[0];
            int bi = wii[0];
            #pragma unroll
            for (int k = 1; k < 8; k++)
                if (wvv[k] < bv || (wvv[k] == bv && wii[k] < bi)) { bv = wvv[k]; bi = wii[k]; }
            winv_s = bv;
            wini_s = bi;
        }
        __syncthreads();
        float bv = winv_s;
        int bi = wini_s;
        if (it == 10) sel10 = bv;
        if (it == 29) sel29 = bv;
        if ((bi >> 4) == tid) {
            int sl = bi & 15;
            #pragma unroll
            for (int k = 0; k < 16; k++)
                if (k == sl) dv[k] = FLT_MAX;
        }
        __syncthreads();
    }
    if (tid == 0) {
        float mdp = __fadd_rn(sqrtf(sel10), 1e-10f);
        uth_out[h * NN + i] = sel29;
        inv2_out[h * NN + i] = 1.0f / (mdp * mdp);
    }
}

// ---------------- paired-tile fused aff + transpose-add (threshold on u) ----------------
__global__ void afftrans_pair(const float* __restrict__ Ab, float* __restrict__ Mb,
                              const float* __restrict__ qn, const float* __restrict__ kn,
                              const float* __restrict__ uth, const float* __restrict__ inv2)
{
    __shared__ float TA[32][33];
    __shared__ float TB[32][33];
    __shared__ float V[32][33];
    int hh = blockIdx.y;
    const float* G = Ab + (size_t)hh * NN * NN;
    float* M = Mb + (size_t)hh * NN * NN;
    const float* qnh = qn + hh * NN;
    const float* knh = kn + hh * NN;
    const float* uthh = uth + hh * NN;
    const float* inv2h = inv2 + hh * NN;

    int p = blockIdx.x;
    int b = (int)((sqrtf(8.0f * (float)p + 1.0f) - 1.0f) * 0.5f);
    while ((b + 1) * (b + 2) / 2 <= p) b++;
    while (b * (b + 1) / 2 > p) b--;
    int a = p - b * (b + 1) / 2;
    int a32 = a * 32, b32 = b * 32;

    int tx = threadIdx.x;
    int ty = threadIdx.y;
    for (int r = ty; r < 32; r += 8) {
        TA[r][tx] = G[(size_t)(a32 + r) * NN + b32 + tx];
        TB[r][tx] = G[(size_t)(b32 + r) * NN + a32 + tx];
    }
    __syncthreads();

    int j = b32 + tx;
    float qnj = qnh[j], knj = knh[j], uthj = uthh[j], inv2j = inv2h[j];
    for (int r = ty; r < 32; r += 8) {
        int i = a32 + r;
        float u1 = usq(qnh[i], knj, TA[r][tx]);
        float u2 = usq(qnj, knh[i], TB[tx][r]);
        bool k1 = (u1 <= uthh[i]);
        bool k2 = (u2 <= uthj);
        float r1 = 0.0f, r2 = 0.0f;
        if (__any_sync(0xffffffffu, k1 | k2)) {
            if (k1) r1 = __expf(-(u1 * inv2h[i]));
            if (k2) r2 = __expf(-(u2 * inv2j));
        }
        V[r][tx] = (i == j) ? 2.0f : (r1 + r2);
    }
    __syncthreads();

    for (int r = ty; r < 32; r += 8)
        M[(size_t)(a32 + r) * NN + b32 + tx] = V[r][tx];
    if (a != b)
        for (int r = ty; r < 32; r += 8)
            M[(size_t)(b32 + r) * NN + a32 + tx] = V[tx][r];
}

// ---------------- sparse build (float4 reads); writes m_0 = 1/Z ----------------
__global__ void build_sparse_b(const float* __restrict__ Mb, int* __restrict__ cols,
                               float* __restrict__ wv, int* __restrict__ cnt,
                               float* __restrict__ Z, float* __restrict__ m)
{
    int i = blockIdx.x;
    int h = blockIdx.y;
    int t = threadIdx.x;
    __shared__ int sc[256];
    __shared__ float zr[256];
    const float4* Mi4 = (const float4*)(Mb + (size_t)h * NN * NN + (size_t)i * NN);
    float mv[16];
    #pragma unroll
    for (int b = 0; b < 4; b++) {
        float4 x = Mi4[t * 4 + b];
        mv[b * 4 + 0] = x.x; mv[b * 4 + 1] = x.y;
        mv[b * 4 + 2] = x.z; mv[b * 4 + 3] = x.w;
    }
    int c = 0;
    float zs = 0.0f;
    #pragma unroll
    for (int k = 0; k < 16; k++)
        if (mv[k] != 0.0f) { c++; zs += expf(mv[k]); }
    sc[t] = c;
    zr[t] = zs;
    __syncthreads();
    for (int d = 1; d < 256; d <<= 1) {
        int x = (t >= d) ? sc[t - d] : 0;
        __syncthreads();
        sc[t] += x;
        __syncthreads();
    }
    int off = sc[t] - c;
    int total = sc[255];
    int p = 0;
    int* ci = cols + ((size_t)h * NN + i) * SPW;
    float* wi = wv + ((size_t)h * NN + i) * SPW;
    #pragma unroll
    for (int k = 0; k < 16; k++) {
        float v = mv[k];
        if (v != 0.0f) {
            int o = off + p;
            if (o < SPW) { ci[o] = t * 16 + k; wi[o] = expf(v) - 1.0f; }
            p++;
        }
    }
    __syncthreads();
    for (int s = 128; s > 0; s >>= 1) {
        if (t < s) zr[t] += zr[t + s];
        __syncthreads();
    }
    if (t == 0) {
        int tt = total > SPW ? SPW : total;
        cnt[h * NN + i] = tt;
        float z = (float)(NN - total) + zr[0];
        Z[h * NN + i] = z;
        m[(size_t)h * 6 * NN + i] = 1.0f / z;
    }
}

// ---------------- sparse N-vector matvec ----------------
__global__ __launch_bounds__(256) void matvec_b(
    const int* __restrict__ cols, const float* __restrict__ wv,
    const int* __restrict__ cnt, const float* __restrict__ Z,
    const float* __restrict__ m, int tin, int tout)
{
    int wid = threadIdx.x >> 5;
    int lane = threadIdx.x & 31;
    int i = blockIdx.x * 8 + wid;
    int h = blockIdx.y;
    int idx = h * NN + i;
    const float* mh = m + ((size_t)h * 6 + tin) * NN;
    const int* ci = cols + (size_t)idx * SPW;
    const float* wi = wv + (size_t)idx * SPW;
    int n = cnt[idx];
    float s = 0.0f;
    for (int k = lane; k < n; k += 32)
        s += wi[k] * mh[ci[k]];
    #pragma unroll
    for (int o = 16; o > 0; o >>= 1)
        s += __shfl_down_sync(0xffffffff, s, o);
    if (lane == 0) {
        float* mo = const_cast<float*>(m) + ((size_t)h * 6 + tout) * NN;
        mo[i] = s / Z[idx];
    }
}

// ---------------- weighted 6-colsum of X ----------------
__global__ void rpart_kernel(const float* __restrict__ X, const float* __restrict__ m,
                             const float* __restrict__ Z, float* __restrict__ part)
{
    int col = blockIdx.x * 256 + threadIdx.x;
    int slab = blockIdx.y;
    int h = blockIdx.z;
    __shared__ float wz[6][128];
    for (int u = threadIdx.x; u < 768; u += 256) {
        int t = u >> 7, rr = u & 127;
        int i = slab * 128 + rr;
        wz[t][rr] = Z[h * NN + i] * m[((size_t)h * 6 + t) * NN + i];
    }
    __syncthreads();
    float acc[6] = {0, 0, 0, 0, 0, 0};
    for (int rr = 0; rr < 128; rr++) {
        float x = X[(size_t)(slab * 128 + rr) * DD + col];
        #pragma unroll
        for (int t = 0; t < 6; t++)
            acc[t] = fmaf(wz[t][rr], x, acc[t]);
    }
    #pragma unroll
    for (int t = 0; t < 6; t++)
        part[((((size_t)h * 32 + slab) * 6) + t) * DD + col] = acc[t];
}

__global__ void rfin_kernel(const float* __restrict__ part, float* __restrict__ r)
{
    int col = blockIdx.x * 256 + threadIdx.x;
    int h = blockIdx.y;
    float a[6] = {0, 0, 0, 0, 0, 0};
    for (int s = 0; s < 32; s++)
        #pragma unroll
        for (int t = 0; t < 6; t++)
            a[t] += part[((((size_t)h * 32 + s) * 6) + t) * DD + col];
    #pragma unroll
    for (int t = 0; t < 6; t++)
        r[((size_t)h * 6 + t) * DD + col] = a[t];
}

__global__ void gsum_kernel(const float* __restrict__ m, float* __restrict__ g)
{
    int h = blockIdx.x;
    int tid = threadIdx.x;
    __shared__ float red[256];
    for (int a = 0; a < 5; a++) {
        const float* ma = m + ((size_t)h * 6 + a) * NN;
        float s = 0.0f;
        for (int i = tid; i < NN; i += 256) s += ma[i];
        red[tid] = s;
        __syncthreads();
        for (int st = 128; st > 0; st >>= 1) {
            if (tid < st) red[tid] += red[tid + st];
            __syncthreads();
        }
        if (tid == 0) g[h * 5 + a] = red[0];
        __syncthreads();
    }
}

__global__ void srec_kernel(const float* __restrict__ r, const float* __restrict__ g,
                            float* __restrict__ s)
{
    int d = blockIdx.x * 256 + threadIdx.x;
    int h = blockIdx.y;
    float g0 = g[h * 5 + 0], g1 = g[h * 5 + 1], g2 = g[h * 5 + 2];
    float g3 = g[h * 5 + 3], g4 = g[h * 5 + 4];
    const float* rh = r + (size_t)h * 6 * DD;
    float r0 = rh[0 * DD + d], r1 = rh[1 * DD + d], r2 = rh[2 * DD + d];
    float r3 = rh[3 * DD + d], r4 = rh[4 * DD + d], r5 = rh[5 * DD + d];
    float s1 = r0;
    float s2 = r1 + g0 * s1;
    float s3 = r2 + g0 * s2 + g1 * s1;
    float s4 = r3 + g0 * s3 + g1 * s2 + g2 * s1;
    float s5 = r4 + g0 * s4 + g1 * s3 + g2 * s2 + g3 * s1;
    float s6 = r5 + g0 * s5 + g1 * s4 + g2 * s3 + g3 * s2 + g4 * s1;
    float* sh = s + (size_t)h * 7 * DD;
    sh[1 * DD + d] = s1;
    sh[2 * DD + d] = s2;
    sh[3 * DD + d] = s3;
    sh[4 * DD + d] = s4;
    sh[5 * DD + d] = s5;
    sh[6 * DD + d] = s6;
}

__global__ __launch_bounds__(256) void final_kernel(
    const float* __restrict__ m, const float* __restrict__ s, float* __restrict__ out)
{
    int i = blockIdx.x;
    int d0 = threadIdx.x * 8;
    __shared__ float sm[24];
    if (threadIdx.x < 24) {
        int h = threadIdx.x / 6, a = threadIdx.x % 6;
        sm[threadIdx.x] = m[((size_t)h * 6 + a) * NN + i];
    }
    __syncthreads();
    float o[8] = {0, 0, 0, 0, 0, 0, 0, 0};
    #pragma unroll
    for (int h = 0; h < HEADS; h++) {
        #pragma unroll
        for (int a = 0; a < 6; a++) {
            float mv = sm[h * 6 + a];
            const float* sv = s + ((size_t)h * 7 + (6 - a)) * DD + d0;
            #pragma unroll
            for (int q = 0; q < 8; q++)
                o[q] = fmaf(mv, sv[q], o[q]);
        }
    }
    float* op = out + (size_t)i * DD + d0;
    #pragma unroll
    for (int q = 0; q < 8; q++) op[q] = 0.25f * o[q];
}

// ---------------- launch ----------------
extern "C" void kernel_launch(void* const* d_in, const int* in_sizes, int n_in,
                              void* d_out, int out_size)
{
    const float* X  = (const float*)d_in[0];
    const float* Wq = (const float*)d_in[1];
    const float* bq = (const float*)d_in[2];
    const float* Wk = (const float*)d_in[3];
    const float* bk = (const float*)d_in[4];
    float* out = (float*)d_out;

    static int smem_set = 0;
    if (!smem_set) {
        cudaFuncSetAttribute(mma_gemm_nt, cudaFuncAttributeMaxDynamicSharedMemorySize,
                             GEMM_SMEM);
        smem_set = 1;
    }

    float *QK, *qn, *kn, *uth, *inv2, *A, *M;
    float *wv, *Z, *m, *g, *rpart, *r, *s;
    int *cols, *cnt;
    __nv_bfloat16 *Xa, *Wall, *Qa, *Kb;
    cudaGetSymbolAddress((void**)&QK,   g_QK);
    cudaGetSymbolAddress((void**)&qn,   g_qn);
    cudaGetSymbolAddress((void**)&kn,   g_kn);
    cudaGetSymbolAddress((void**)&uth,  g_uth);
    cudaGetSymbolAddress((void**)&inv2, g_inv2);
    cudaGetSymbolAddress((void**)&A,    g_A);
    cudaGetSymbolAddress((void**)&M,    g_M);
    cudaGetSymbolAddress((void**)&cols, g_cols);
    cudaGetSymbolAddress((void**)&wv,   g_wv);
    cudaGetSymbolAddress((void**)&cnt,  g_cnt);
    cudaGetSymbolAddress((void**)&Z,    g_Z);
    cudaGetSymbolAddress((void**)&m,    g_m);
    cudaGetSymbolAddress((void**)&g,    g_g);
    cudaGetSymbolAddress((void**)&rpart, g_rpart);
    cudaGetSymbolAddress((void**)&r,    g_r);
    cudaGetSymbolAddress((void**)&s,    g_s);
    cudaGetSymbolAddress((void**)&Xa,   s_Xa);
    cudaGetSymbolAddress((void**)&Wall, s_Wall);
    cudaGetSymbolAddress((void**)&Qa,   s_Qa);
    cudaGetSymbolAddress((void**)&Kb,   s_Kb);

    const size_t SA = (size_t)NN * K2HH;
    const size_t SC = (size_t)NN * NN;

    // ---- setup ----
    split_kernel4<<<(NN * DD / 4 + 255) / 256, 256>>>(
        (const float4*)X, (ushort4*)Xa, NN * DD / 4, 9, 1);
    split_kernel4<<<(1024 * DD / 4 + 255) / 256, 256>>>(
        (const float4*)Wq, (ushort4*)Wall, 1024 * DD / 4, 9, 0);
    split_kernel4<<<(1024 * DD / 4 + 255) / 256, 256>>>(
        (const float4*)Wk, (ushort4*)(Wall + (size_t)1024 * K3DD), 1024 * DD / 4, 9, 0);

    // combined projections with fused bias
    mma_gemm_nt<<<dim3(NQK / BN, NN / BM, 1), 256, GEMM_SMEM>>>(
        Xa, Wall, QK, NN, NQK, K3DD, NQK, 0, 0, 0, bq, bk);

    // ---- per-head phases (batched) ----
    rownorm_b<<<dim3(NN, HEADS), 256>>>(QK, qn, kn);
    split2_strided4<<<dim3((NN * 64 + 255) / 256, HEADS), 256>>>(QK, 0, (ushort4*)Qa, 1);
    split2_strided4<<<dim3((NN * 64 + 255) / 256, HEADS), 256>>>(QK, 1024, (ushort4*)Kb, 0);
    mma_gemm_nt<<<dim3(NN / BN, NN / BM, HEADS), 256, GEMM_SMEM>>>(
        Qa, Kb, A, NN, NN, K2HH, NN, SA, SA, SC, nullptr, nullptr);

    select_b<<<dim3(NN, HEADS), 256>>>(A, qn, kn, uth, inv2);
    afftrans_pair<<<dim3(PAIRS, HEADS), dim3(32, 8)>>>(A, M, qn, kn, uth, inv2);
    build_sparse_b<<<dim3(NN, HEADS), 256>>>(M, cols, wv, cnt, Z, m);

    // ---- rank-1 decomposition path ----
    for (int t = 0; t < 5; t++)
        matvec_b<<<dim3(NN / 8, HEADS), 256>>>(cols, wv, cnt, Z, m, t, t + 1);

    rpart_kernel<<<dim3(8, 32, HEADS), 256>>>(X, m, Z, rpart);
    rfin_kernel<<<dim3(8, HEADS), 256>>>(rpart, r);
    gsum_kernel<<<HEADS, 256>>>(m, g);
    srec_kernel<<<dim3(8, HEADS), 256>>>(r, g, s);
    final_kernel<<<NN, 256>>>(m, s, out);
}

// round 17
// speedup vs baseline: 1.0041x; 1.0041x over previous
#include <cuda_runtime.h>
#include <cuda_bf16.h>
#include <math.h>
#include <float.h>
#include <stdint.h>

#define NN 4096
#define DD 2048
#define HH 256
#define HEADS 4
#define K3DD (3*2048)
#define K2HH (2*256)
#define NQK 2048
#define SPW 2048
#define PAIRS 8256   // 128*129/2

// ---------------- static device scratch ----------------
__device__ float g_QK[(size_t)NN * NQK];
__device__ float g_qn[HEADS * NN];
__device__ float g_kn[HEADS * NN];
__device__ float g_uth[HEADS * NN];    // 30th-smallest u per row
__device__ float g_inv2[HEADS * NN];   // 1/(md+1e-10)^2 per row
__device__ float g_A[(size_t)HEADS * NN * NN];
__device__ float g_M[(size_t)HEADS * NN * NN];

__device__ int   g_cols[(size_t)HEADS * NN * SPW];
__device__ float g_wv[(size_t)HEADS * NN * SPW];
__device__ int   g_cnt[HEADS * NN];
__device__ float g_Z[HEADS * NN];

__device__ float g_m[HEADS * 6 * NN];
__device__ float g_g[HEADS * 5];
__device__ float g_rpart[(size_t)HEADS * 32 * 6 * DD];
__device__ float g_r[HEADS * 6 * DD];
__device__ float g_s[HEADS * 7 * DD];

__device__ __nv_bfloat16 s_Xa[(size_t)NN * K3DD];
__device__ __nv_bfloat16 s_Wall[(size_t)NQK * K3DD];
__device__ __nv_bfloat16 s_Qa[(size_t)HEADS * NN * K2HH];
__device__ __nv_bfloat16 s_Kb[(size_t)HEADS * NN * K2HH];

// shared u formula — must be bit-identical in select and afftrans
__device__ __forceinline__ float usq(float qni, float knj, float g) {
    float t = __fadd_rn(qni, knj);
    t = __fadd_rn(t, __fmul_rn(-2.0f, g));
    t = fmaxf(t, 0.0f);
    return __fadd_rn(t, 1e-10f);
}

// ---------------- batched mma.sync NT GEMM: 128x256 CTA, 8 warps, 64x64 warp ----------------
#define BM 128
#define BN 256
#define BK 64
#define STAGES 3
#define PAD 72
#define A_STAGE (BM * PAD * 2)
#define B_STAGE (BN * PAD * 2)
#define STAGE_BYTES (A_STAGE + B_STAGE)
#define GEMM_SMEM (STAGES * STAGE_BYTES)

__device__ __forceinline__ uint32_t smem_u32(const void* p) {
    uint32_t a;
    asm("{ .reg .u64 t; cvta.to.shared.u64 t, %1; cvt.u32.u64 %0, t; }" : "=r"(a) : "l"(p));
    return a;
}
#define CP_ASYNC16(sa, ga) \
    asm volatile("cp.async.cg.shared.global [%0], [%1], 16;" :: "r"(sa), "l"(ga))
#define CP_COMMIT() asm volatile("cp.async.commit_group;" ::: "memory")
#define CP_WAIT1()  asm volatile("cp.async.wait_group 1;" ::: "memory")
#define CP_WAIT0()  asm volatile("cp.async.wait_group 0;" ::: "memory")
#define LDSM_X4(r0, r1, r2, r3, a) \
    asm volatile("ldmatrix.sync.aligned.m8n8.x4.shared.b16 {%0,%1,%2,%3}, [%4];" \
        : "=r"(r0), "=r"(r1), "=r"(r2), "=r"(r3) : "r"(a))
#define MMA16816(c, a0, a1, a2, a3, b0, b1) \
    asm volatile("mma.sync.aligned.m16n8k16.row.col.f32.bf16.bf16.f32 " \
        "{%0,%1,%2,%3}, {%4,%5,%6,%7}, {%8,%9}, {%0,%1,%2,%3};" \
        : "+f"((c)[0]), "+f"((c)[1]), "+f"((c)[2]), "+f"((c)[3]) \
        : "r"(a0), "r"(a1), "r"(a2), "r"(a3), "r"(b0), "r"(b1))

__global__ __launch_bounds__(256) void mma_gemm_nt(
    const __nv_bfloat16* __restrict__ Ab, const __nv_bfloat16* __restrict__ Bb,
    float* __restrict__ Cb, int M, int N, int K, int ldc,
    size_t strideA, size_t strideB, size_t strideC,
    const float* __restrict__ bq, const float* __restrict__ bk)
{
    extern __shared__ __align__(128) char smem[];
    const uint32_t sbase = smem_u32(smem);
    const int tid = threadIdx.x;
    const int wid = tid >> 5;
    const int lane = tid & 31;
    const int wm = (wid & 1) * 64;
    const int wn = (wid >> 1) * 64;

    const __nv_bfloat16* A = Ab + blockIdx.z * strideA;
    const __nv_bfloat16* B = Bb + blockIdx.z * strideB;
    float* C = Cb + blockIdx.z * strideC;

    const int nbx = gridDim.x;
    int id = blockIdx.y * nbx + blockIdx.x;
    int grp = id / (8 * nbx);
    int rem = id - grp * (8 * nbx);
    const int m0 = (grp * 8 + (rem & 7)) * BM;
    const int n0 = (rem >> 3) * BN;

    const __nv_bfloat16* gA = A + (size_t)m0 * K;
    const __nv_bfloat16* gB = B + (size_t)n0 * K;

    const int lrow = tid >> 3;
    const int lcol = (tid & 7) << 3;

    float acc[4][8][4];
    #pragma unroll
    for (int i = 0; i < 4; i++)
        #pragma unroll
        for (int j = 0; j < 8; j++)
            #pragma unroll
            for (int q = 0; q < 4; q++) acc[i][j][q] = 0.0f;

    const int KT = K / BK;

    #pragma unroll
    for (int s = 0; s < STAGES - 1; s++) {
        const int k0 = s * BK;
        uint32_t sa = sbase + s * STAGE_BYTES;
        uint32_t sb = sa + A_STAGE;
        #pragma unroll
        for (int h = 0; h < 4; h++) {
            int r = lrow + h * 32;
            CP_ASYNC16(sa + (uint32_t)(r * PAD + lcol) * 2, gA + (size_t)r * K + k0 + lcol);
        }
        #pragma unroll
        for (int h = 0; h < 8; h++) {
            int r = lrow + h * 32;
            CP_ASYNC16(sb + (uint32_t)(r * PAD + lcol) * 2, gB + (size_t)r * K + k0 + lcol);
        }
        CP_COMMIT();
    }

    const int a_row = wm + (lane & 15);
    const int a_half = (lane >> 4) << 3;
    const int b_row = wn + ((lane >> 4) << 3) + (lane & 7);
    const int b_half = ((lane >> 3) & 1) << 3;

    for (int kt = 0; kt < KT; kt++) {
        CP_WAIT1();
        __syncthreads();

        if (kt + STAGES - 1 < KT) {
            const int s = (kt + STAGES - 1) % STAGES;
            const int k0 = (kt + STAGES - 1) * BK;
            uint32_t sa = sbase + s * STAGE_BYTES;
            uint32_t sb = sa + A_STAGE;
            #pragma unroll
            for (int h = 0; h < 4; h++) {
                int r = lrow + h * 32;
                CP_ASYNC16(sa + (uint32_t)(r * PAD + lcol) * 2, gA + (size_t)r * K + k0 + lcol);
            }
            #pragma unroll
            for (int h = 0; h < 8; h++) {
                int r = lrow + h * 32;
                CP_ASYNC16(sb + (uint32_t)(r * PAD + lcol) * 2, gB + (size_t)r * K + k0 + lcol);
            }
        }
        CP_COMMIT();

        const int s = kt % STAGES;
        const uint32_t sa = sbase + s * STAGE_BYTES;
        const uint32_t sb = sa + A_STAGE;

        #pragma unroll
        for (int kk = 0; kk < 4; kk++) {
            uint32_t a0[4], a1[4], a2[4], a3[4];
            #pragma unroll
            for (int mt = 0; mt < 4; mt++) {
                uint32_t addr = sa + (uint32_t)((a_row + mt * 16) * PAD + kk * 16 + a_half) * 2;
                LDSM_X4(a0[mt], a1[mt], a2[mt], a3[mt], addr);
            }
            uint32_t b[8][2];
            #pragma unroll
            for (int g = 0; g < 4; g++) {
                uint32_t addr = sb + (uint32_t)((b_row + g * 16) * PAD + kk * 16 + b_half) * 2;
                uint32_t r0, r1, r2, r3;
                LDSM_X4(r0, r1, r2, r3, addr);
                b[g * 2 + 0][0] = r0; b[g * 2 + 0][1] = r1;
                b[g * 2 + 1][0] = r2; b[g * 2 + 1][1] = r3;
            }
            #pragma unroll
            for (int mt = 0; mt < 4; mt++)
                #pragma unroll
                for (int nt = 0; nt < 8; nt++)
                    MMA16816(acc[mt][nt], a0[mt], a1[mt], a2[mt], a3[mt],
                             b[nt][0], b[nt][1]);
        }
        __syncthreads();
    }
    CP_WAIT0();

    const int er = lane >> 2;
    const int ec = (lane & 3) << 1;
    #pragma unroll
    for (int mt = 0; mt < 4; mt++) {
        #pragma unroll
        for (int nt = 0; nt < 8; nt++) {
            int col = n0 + wn + nt * 8 + ec;
            float b0 = 0.0f, b1 = 0.0f;
            if (bq) {
                b0 = (col < 1024) ? bq[col] : bk[col - 1024];
                b1 = (col + 1 < 1024) ? bq[col + 1] : bk[col + 1 - 1024];
            }
            #pragma unroll
            for (int half = 0; half < 2; half++) {
                int row = m0 + wm + mt * 16 + er + half * 8;
                float* Cp = C + (size_t)row * ldc + col;
                *(float2*)Cp = make_float2(acc[mt][nt][half * 2 + 0] + b0,
                                           acc[mt][nt][half * 2 + 1] + b1);
            }
        }
    }
}

// ---------------- vectorized splits ----------------
__device__ __forceinline__ unsigned short bfu(__nv_bfloat16 v) {
    return *reinterpret_cast<unsigned short*>(&v);
}

__global__ void split_kernel4(const float4* __restrict__ src, ushort4* __restrict__ dst,
                              int total4, int logC4, int lo_mid)
{
    int idx = blockIdx.x * blockDim.x + threadIdx.x;
    if (idx >= total4) return;
    int C4 = 1 << logC4;
    int r = idx >> logC4;
    int c = idx & (C4 - 1);
    float4 x = src[idx];
    __nv_bfloat16 h0 = __float2bfloat16(x.x), h1 = __float2bfloat16(x.y);
    __nv_bfloat16 h2 = __float2bfloat16(x.z), h3 = __float2bfloat16(x.w);
    __nv_bfloat16 l0 = __float2bfloat16(x.x - __bfloat162float(h0));
    __nv_bfloat16 l1 = __float2bfloat16(x.y - __bfloat162float(h1));
    __nv_bfloat16 l2 = __float2bfloat16(x.z - __bfloat162float(h2));
    __nv_bfloat16 l3 = __float2bfloat16(x.w - __bfloat162float(h3));
    ushort4 hh = make_ushort4(bfu(h0), bfu(h1), bfu(h2), bfu(h3));
    ushort4 ll = make_ushort4(bfu(l0), bfu(l1), bfu(l2), bfu(l3));
    size_t base = (size_t)r * 3 * C4 + c;
    dst[base] = hh;
    dst[base + C4] = lo_mid ? ll : hh;
    dst[base + 2 * C4] = lo_mid ? hh : ll;
}

__global__ void split2_strided4(const float* __restrict__ QK, int base_off,
                                ushort4* __restrict__ dst, int lo_second)
{
    int idx = blockIdx.x * blockDim.x + threadIdx.x;
    if (idx >= NN * (HH / 4)) return;
    int h = blockIdx.y;
    int r = idx >> 6;
    int c = idx & 63;
    float4 x = *(const float4*)(QK + (size_t)r * NQK + base_off + h * HH + c * 4);
    __nv_bfloat16 h0 = __float2bfloat16(x.x), h1 = __float2bfloat16(x.y);
    __nv_bfloat16 h2 = __float2bfloat16(x.z), h3 = __float2bfloat16(x.w);
    ushort4 hh = make_ushort4(bfu(h0), bfu(h1), bfu(h2), bfu(h3));
    ushort4 sec = hh;
    if (lo_second) {
        __nv_bfloat16 l0 = __float2bfloat16(x.x - __bfloat162float(h0));
        __nv_bfloat16 l1 = __float2bfloat16(x.y - __bfloat162float(h1));
        __nv_bfloat16 l2 = __float2bfloat16(x.z - __bfloat162float(h2));
        __nv_bfloat16 l3 = __float2bfloat16(x.w - __bfloat162float(h3));
        sec = make_ushort4(bfu(l0), bfu(l1), bfu(l2), bfu(l3));
    }
    size_t base = (size_t)h * NN * 128 + (size_t)r * 128 + c;
    dst[base] = hh;
    dst[base + 64] = sec;
}

// ---------------- batched: blockIdx.y = head ----------------
__global__ void rownorm_b(const float* __restrict__ QK,
                          float* __restrict__ qn, float* __restrict__ kn)
{
    int i = blockIdx.x;
    int h = blockIdx.y;
    int tid = threadIdx.x;
    __shared__ float sq[256];
    __shared__ float sk[256];
    float q = QK[(size_t)i * NQK + h * HH + tid];
    float k = QK[(size_t)i * NQK + 1024 + h * HH + tid];
    sq[tid] = q * q;
    sk[tid] = k * k;
    __syncthreads();
    for (int s = 128; s > 0; s >>= 1) {
        if (tid < s) { sq[tid] += sq[tid + s]; sk[tid] += sk[tid + s]; }
        __syncthreads();
    }
    if (tid == 0) { qn[h * NN + i] = sq[0]; kn[h * NN + i] = sk[0]; }
}

// ---------------- register-resident selection on u (no per-element sqrt) ----------------
__global__ __launch_bounds__(256) void select_b(
    const float* __restrict__ Ab,
    const float* __restrict__ qn, const float* __restrict__ kn,
    float* __restrict__ uth_out, float* __restrict__ inv2_out)
{
    int i = blockIdx.x;
    int h = blockIdx.y;
    int tid = threadIdx.x;
    int lane = tid & 31;
    int wid = tid >> 5;
    const float* G = Ab + (size_t)h * NN * NN + (size_t)i * NN;
    const float* knh = kn + h * NN;
    float qni = qn[h * NN + i];

    float dv[16];
    const float4* G4 = (const float4*)G;
    const float4* K4 = (const float4*)knh;
    #pragma unroll
    for (int b = 0; b < 4; b++) {
        float4 g = G4[tid * 4 + b];
        float4 k4 = K4[tid * 4 + b];
        dv[b * 4 + 0] = usq(qni, k4.x, g.x);
        dv[b * 4 + 1] = usq(qni, k4.y, g.y);
        dv[b * 4 + 2] = usq(qni, k4.z, g.z);
        dv[b * 4 + 3] = usq(qni, k4.w, g.w);
    }

    __shared__ float wvv[8];
    __shared__ int wii[8];
    __shared__ float winv_s;
    __shared__ int wini_s;
    float sel10 = 0.0f, sel29 = 0.0f;

    for (int it = 0; it < 30; it++) {
        float v = dv[0];
        int li = 0;
        #pragma unroll
        for (int k = 1; k < 16; k++)
            if (dv[k] < v) { v = dv[k]; li = k; }
        int gi = tid * 16 + li;
        #pragma unroll
        for (int o = 16; o; o >>= 1) {
            float v2 = __shfl_down_sync(0xffffffffu, v, o);
            int i2 = __shfl_down_sync(0xffffffffu, gi, o);
            if (v2 < v || (v2 == v && i2 < gi)) { v = v2; gi = i2; }
        }
        if (lane == 0) { wvv[wid] = v; wii[wid] = gi; }
        __syncthreads();
        if (tid == 0) {
            float bv = wvv[0];
            int bi = wii[0];
            #pragma unroll
            for (int k = 1; k < 8; k++)
                if (wvv[k] < bv || (wvv[k] == bv && wii[k] < bi)) { bv = wvv[k]; bi = wii[k]; }
            winv_s = bv;
            wini_s = bi;
        }
        __syncthreads();
        float bv = winv_s;
        int bi = wini_s;
        if (it == 10) sel10 = bv;
        if (it == 29) sel29 = bv;
        if ((bi >> 4) == tid) {
            int sl = bi & 15;
            #pragma unroll
            for (int k = 0; k < 16; k++)
                if (k == sl) dv[k] = FLT_MAX;
        }
        __syncthreads();
    }
    if (tid == 0) {
        float mdp = __fadd_rn(sqrtf(sel10), 1e-10f);
        uth_out[h * NN + i] = sel29;
        inv2_out[h * NN + i] = 1.0f / (mdp * mdp);
    }
}

// ---------------- paired-tile fused aff + transpose-add (threshold on u) ----------------
__global__ void afftrans_pair(const float* __restrict__ Ab, float* __restrict__ Mb,
                              const float* __restrict__ qn, const float* __restrict__ kn,
                              const float* __restrict__ uth, const float* __restrict__ inv2)
{
    __shared__ float TA[32][33];
    __shared__ float TB[32][33];
    __shared__ float V[32][33];
    int hh = blockIdx.y;
    const float* G = Ab + (size_t)hh * NN * NN;
    float* M = Mb + (size_t)hh * NN * NN;
    const float* qnh = qn + hh * NN;
    const float* knh = kn + hh * NN;
    const float* uthh = uth + hh * NN;
    const float* inv2h = inv2 + hh * NN;

    int p = blockIdx.x;
    int b = (int)((sqrtf(8.0f * (float)p + 1.0f) - 1.0f) * 0.5f);
    while ((b + 1) * (b + 2) / 2 <= p) b++;
    while (b * (b + 1) / 2 > p) b--;
    int a = p - b * (b + 1) / 2;
    int a32 = a * 32, b32 = b * 32;

    int tx = threadIdx.x;
    int ty = threadIdx.y;
    for (int r = ty; r < 32; r += 8) {
        TA[r][tx] = G[(size_t)(a32 + r) * NN + b32 + tx];
        TB[r][tx] = G[(size_t)(b32 + r) * NN + a32 + tx];
    }
    __syncthreads();

    int j = b32 + tx;
    float qnj = qnh[j], knj = knh[j], uthj = uthh[j], inv2j = inv2h[j];
    for (int r = ty; r < 32; r += 8) {
        int i = a32 + r;
        float u1 = usq(qnh[i], knj, TA[r][tx]);
        float u2 = usq(qnj, knh[i], TB[tx][r]);
        bool k1 = (u1 <= uthh[i]);
        bool k2 = (u2 <= uthj);
        float r1 = 0.0f, r2 = 0.0f;
        if (__any_sync(0xffffffffu, k1 | k2)) {
            if (k1) r1 = __expf(-(u1 * inv2h[i]));
            if (k2) r2 = __expf(-(u2 * inv2j));
        }
        V[r][tx] = (i == j) ? 2.0f : (r1 + r2);
    }
    __syncthreads();

    for (int r = ty; r < 32; r += 8)
        M[(size_t)(a32 + r) * NN + b32 + tx] = V[r][tx];
    if (a != b)
        for (int r = ty; r < 32; r += 8)
            M[(size_t)(b32 + r) * NN + a32 + tx] = V[tx][r];
}

// ---------------- sparse build (float4 reads); writes m_0 = 1/Z ----------------
__global__ void build_sparse_b(const float* __restrict__ Mb, int* __restrict__ cols,
                               float* __restrict__ wv, int* __restrict__ cnt,
                               float* __restrict__ Z, float* __restrict__ m)
{
    int i = blockIdx.x;
    int h = blockIdx.y;
    int t = threadIdx.x;
    __shared__ int sc[256];
    __shared__ float zr[256];
    const float4* Mi4 = (const float4*)(Mb + (size_t)h * NN * NN + (size_t)i * NN);
    float mv[16];
    #pragma unroll
    for (int b = 0; b < 4; b++) {
        float4 x = Mi4[t * 4 + b];
        mv[b * 4 + 0] = x.x; mv[b * 4 + 1] = x.y;
        mv[b * 4 + 2] = x.z; mv[b * 4 + 3] = x.w;
    }
    int c = 0;
    float zs = 0.0f;
    #pragma unroll
    for (int k = 0; k < 16; k++)
        if (mv[k] != 0.0f) { c++; zs += expf(mv[k]); }
    sc[t] = c;
    zr[t] = zs;
    __syncthreads();
    for (int d = 1; d < 256; d <<= 1) {
        int x = (t >= d) ? sc[t - d] : 0;
        __syncthreads();
        sc[t] += x;
        __syncthreads();
    }
    int off = sc[t] - c;
    int total = sc[255];
    int p = 0;
    int* ci = cols + ((size_t)h * NN + i) * SPW;
    float* wi = wv + ((size_t)h * NN + i) * SPW;
    #pragma unroll
    for (int k = 0; k < 16; k++) {
        float v = mv[k];
        if (v != 0.0f) {
            int o = off + p;
            if (o < SPW) { ci[o] = t * 16 + k; wi[o] = expf(v) - 1.0f; }
            p++;
        }
    }
    __syncthreads();
    for (int s = 128; s > 0; s >>= 1) {
        if (t < s) zr[t] += zr[t + s];
        __syncthreads();
    }
    if (t == 0) {
        int tt = total > SPW ? SPW : total;
        cnt[h * NN + i] = tt;
        float z = (float)(NN - total) + zr[0];
        Z[h * NN + i] = z;
        m[(size_t)h * 6 * NN + i] = 1.0f / z;
    }
}

// ---------------- sparse N-vector matvec ----------------
__global__ __launch_bounds__(256) void matvec_b(
    const int* __restrict__ cols, const float* __restrict__ wv,
    const int* __restrict__ cnt, const float* __restrict__ Z,
    const float* __restrict__ m, int tin, int tout)
{
    int wid = threadIdx.x >> 5;
    int lane = threadIdx.x & 31;
    int i = blockIdx.x * 8 + wid;
    int h = blockIdx.y;
    int idx = h * NN + i;
    const float* mh = m + ((size_t)h * 6 + tin) * NN;
    const int* ci = cols + (size_t)idx * SPW;
    const float* wi = wv + (size_t)idx * SPW;
    int n = cnt[idx];
    float s = 0.0f;
    for (int k = lane; k < n; k += 32)
        s += wi[k] * mh[ci[k]];
    #pragma unroll
    for (int o = 16; o > 0; o >>= 1)
        s += __shfl_down_sync(0xffffffff, s, o);
    if (lane == 0) {
        float* mo = const_cast<float*>(m) + ((size_t)h * 6 + tout) * NN;
        mo[i] = s / Z[idx];
    }
}

// ---------------- weighted 6-colsum of X ----------------
__global__ void rpart_kernel(const float* __restrict__ X, const float* __restrict__ m,
                             const float* __restrict__ Z, float* __restrict__ part)
{
    int col = blockIdx.x * 256 + threadIdx.x;
    int slab = blockIdx.y;
    int h = blockIdx.z;
    __shared__ float wz[6][128];
    for (int u = threadIdx.x; u < 768; u += 256) {
        int t = u >> 7, rr = u & 127;
        int i = slab * 128 + rr;
        wz[t][rr] = Z[h * NN + i] * m[((size_t)h * 6 + t) * NN + i];
    }
    __syncthreads();
    float acc[6] = {0, 0, 0, 0, 0, 0};
    for (int rr = 0; rr < 128; rr++) {
        float x = X[(size_t)(slab * 128 + rr) * DD + col];
        #pragma unroll
        for (int t = 0; t < 6; t++)
            acc[t] = fmaf(wz[t][rr], x, acc[t]);
    }
    #pragma unroll
    for (int t = 0; t < 6; t++)
        part[((((size_t)h * 32 + slab) * 6) + t) * DD + col] = acc[t];
}

__global__ void rfin_kernel(const float* __restrict__ part, float* __restrict__ r)
{
    int col = blockIdx.x * 256 + threadIdx.x;
    int h = blockIdx.y;
    float a[6] = {0, 0, 0, 0, 0, 0};
    for (int s = 0; s < 32; s++)
        #pragma unroll
        for (int t = 0; t < 6; t++)
            a[t] += part[((((size_t)h * 32 + s) * 6) + t) * DD + col];
    #pragma unroll
    for (int t = 0; t < 6; t++)
        r[((size_t)h * 6 + t) * DD + col] = a[t];
}

__global__ void gsum_kernel(const float* __restrict__ m, float* __restrict__ g)
{
    int h = blockIdx.x;
    int tid = threadIdx.x;
    __shared__ float red[256];
    for (int a = 0; a < 5; a++) {
        const float* ma = m + ((size_t)h * 6 + a) * NN;
        float s = 0.0f;
        for (int i = tid; i < NN; i += 256) s += ma[i];
        red[tid] = s;
        __syncthreads();
        for (int st = 128; st > 0; st >>= 1) {
            if (tid < st) red[tid] += red[tid + st];
            __syncthreads();
        }
        if (tid == 0) g[h * 5 + a] = red[0];
        __syncthreads();
    }
}

__global__ void srec_kernel(const float* __restrict__ r, const float* __restrict__ g,
                            float* __restrict__ s)
{
    int d = blockIdx.x * 256 + threadIdx.x;
    int h = blockIdx.y;
    float g0 = g[h * 5 + 0], g1 = g[h * 5 + 1], g2 = g[h * 5 + 2];
    float g3 = g[h * 5 + 3], g4 = g[h * 5 + 4];
    const float* rh = r + (size_t)h * 6 * DD;
    float r0 = rh[0 * DD + d], r1 = rh[1 * DD + d], r2 = rh[2 * DD + d];
    float r3 = rh[3 * DD + d], r4 = rh[4 * DD + d], r5 = rh[5 * DD + d];
    float s1 = r0;
    float s2 = r1 + g0 * s1;
    float s3 = r2 + g0 * s2 + g1 * s1;
    float s4 = r3 + g0 * s3 + g1 * s2 + g2 * s1;
    float s5 = r4 + g0 * s4 + g1 * s3 + g2 * s2 + g3 * s1;
    float s6 = r5 + g0 * s5 + g1 * s4 + g2 * s3 + g3 * s2 + g4 * s1;
    float* sh = s + (size_t)h * 7 * DD;
    sh[1 * DD + d] = s1;
    sh[2 * DD + d] = s2;
    sh[3 * DD + d] = s3;
    sh[4 * DD + d] = s4;
    sh[5 * DD + d] = s5;
    sh[6 * DD + d] = s6;
}

__global__ __launch_bounds__(256) void final_kernel(
    const float* __restrict__ m, const float* __restrict__ s, float* __restrict__ out)
{
    int i = blockIdx.x;
    int d0 = threadIdx.x * 8;
    __shared__ float sm[24];
    if (threadIdx.x < 24) {
        int h = threadIdx.x / 6, a = threadIdx.x % 6;
        sm[threadIdx.x] = m[((size_t)h * 6 + a) * NN + i];
    }
    __syncthreads();
    float o[8] = {0, 0, 0, 0, 0, 0, 0, 0};
    #pragma unroll
    for (int h = 0; h < HEADS; h++) {
        #pragma unroll
        for (int a = 0; a < 6; a++) {
            float mv = sm[h * 6 + a];
            const float* sv = s + ((size_t)h * 7 + (6 - a)) * DD + d0;
            #pragma unroll
            for (int q = 0; q < 8; q++)
                o[q] = fmaf(mv, sv[q], o[q]);
        }
    }
    float* op = out + (size_t)i * DD + d0;
    #pragma unroll
    for (int q = 0; q < 8; q++) op[q] = 0.25f * o[q];
}

// ---------------- launch ----------------
extern "C" void kernel_launch(void* const* d_in, const int* in_sizes, int n_in,
                              void* d_out, int out_size)
{
    const float* X  = (const float*)d_in[0];
    const float* Wq = (const float*)d_in[1];
    const float* bq = (const float*)d_in[2];
    const float* Wk = (const float*)d_in[3];
    const float* bk = (const float*)d_in[4];
    float* out = (float*)d_out;

    static int smem_set = 0;
    if (!smem_set) {
        cudaFuncSetAttribute(mma_gemm_nt, cudaFuncAttributeMaxDynamicSharedMemorySize,
                             GEMM_SMEM);
        smem_set = 1;
    }

    float *QK, *qn, *kn, *uth, *inv2, *A, *M;
    float *wv, *Z, *m, *g, *rpart, *r, *s;
    int *cols, *cnt;
    __nv_bfloat16 *Xa, *Wall, *Qa, *Kb;
    cudaGetSymbolAddress((void**)&QK,   g_QK);
    cudaGetSymbolAddress((void**)&qn,   g_qn);
    cudaGetSymbolAddress((void**)&kn,   g_kn);
    cudaGetSymbolAddress((void**)&uth,  g_uth);
    cudaGetSymbolAddress((void**)&inv2, g_inv2);
    cudaGetSymbolAddress((void**)&A,    g_A);
    cudaGetSymbolAddress((void**)&M,    g_M);
    cudaGetSymbolAddress((void**)&cols, g_cols);
    cudaGetSymbolAddress((void**)&wv,   g_wv);
    cudaGetSymbolAddress((void**)&cnt,  g_cnt);
    cudaGetSymbolAddress((void**)&Z,    g_Z);
    cudaGetSymbolAddress((void**)&m,    g_m);
    cudaGetSymbolAddress((void**)&g,    g_g);
    cudaGetSymbolAddress((void**)&rpart, g_rpart);
    cudaGetSymbolAddress((void**)&r,    g_r);
    cudaGetSymbolAddress((void**)&s,    g_s);
    cudaGetSymbolAddress((void**)&Xa,   s_Xa);
    cudaGetSymbolAddress((void**)&Wall, s_Wall);
    cudaGetSymbolAddress((void**)&Qa,   s_Qa);
    cudaGetSymbolAddress((void**)&Kb,   s_Kb);

    const size_t SA = (size_t)NN * K2HH;
    const size_t SC = (size_t)NN * NN;

    // ---- setup ----
    split_kernel4<<<(NN * DD / 4 + 255) / 256, 256>>>(
        (const float4*)X, (ushort4*)Xa, NN * DD / 4, 9, 1);
    split_kernel4<<<(1024 * DD / 4 + 255) / 256, 256>>>(
        (const float4*)Wq, (ushort4*)Wall, 1024 * DD / 4, 9, 0);
    split_kernel4<<<(1024 * DD / 4 + 255) / 256, 256>>>(
        (const float4*)Wk, (ushort4*)(Wall + (size_t)1024 * K3DD), 1024 * DD / 4, 9, 0);

    // combined projections with fused bias
    mma_gemm_nt<<<dim3(NQK / BN, NN / BM, 1), 256, GEMM_SMEM>>>(
        Xa, Wall, QK, NN, NQK, K3DD, NQK, 0, 0, 0, bq, bk);

    // ---- per-head phases (batched) ----
    rownorm_b<<<dim3(NN, HEADS), 256>>>(QK, qn, kn);
    split2_strided4<<<dim3((NN * 64 + 255) / 256, HEADS), 256>>>(QK, 0, (ushort4*)Qa, 1);
    split2_strided4<<<dim3((NN * 64 + 255) / 256, HEADS), 256>>>(QK, 1024, (ushort4*)Kb, 0);
    mma_gemm_nt<<<dim3(NN / BN, NN / BM, HEADS), 256, GEMM_SMEM>>>(
        Qa, Kb, A, NN, NN, K2HH, NN, SA, SA, SC, nullptr, nullptr);

    select_b<<<dim3(NN, HEADS), 256>>>(A, qn, kn, uth, inv2);
    afftrans_pair<<<dim3(PAIRS, HEADS), dim3(32, 8)>>>(A, M, qn, kn, uth, inv2);
    build_sparse_b<<<dim3(NN, HEADS), 256>>>(M, cols, wv, cnt, Z, m);

    // ---- rank-1 decomposition path ----
    for (int t = 0; t < 5; t++)
        matvec_b<<<dim3(NN / 8, HEADS), 256>>>(cols, wv, cnt, Z, m, t, t + 1);

    rpart_kernel<<<dim3(8, 32, HEADS), 256>>>(X, m, Z, rpart);
    rfin_kernel<<<dim3(8, HEADS), 256>>>(rpart, r);
    gsum_kernel<<<HEADS, 256>>>(m, g);
    srec_kernel<<<dim3(8, HEADS), 256>>>(r, g, s);
    final_kernel<<<NN, 256>>>(m, s, out);
}